// round 7
// baseline (speedup 1.0000x reference)
#include <cuda_runtime.h>

#define UL unsigned long long

// Scratch (no allocs allowed).
__device__ float g_abp[4 * 2 * 512 * 768];       // [ksplit][z][b*S+row][H] partials
__device__ float g_ab[2 * 512 * 768];            // [z][b*S+row][H]  (z=0: ha+b1, z=1: hb)
__device__ float g_part[8 * 4 * 128 * 128 * 2];  // [hsplit][b][s][t][o]

__device__ __forceinline__ UL pack_dup(float x) {
    unsigned xi = __float_as_uint(x);
    UL r; asm("mov.b64 %0, {%1, %1};" : "=l"(r) : "r"(xi)); return r;
}
__device__ __forceinline__ UL fma2(UL a, UL b, UL c) {
    UL d; asm("fma.rn.f32x2 %0, %1, %2, %3;" : "=l"(d) : "l"(a), "l"(b), "l"(c)); return d;
}
__device__ __forceinline__ UL add2(UL a, UL b) {
    UL d; asm("add.rn.f32x2 %0, %1, %2;" : "=l"(d) : "l"(a), "l"(b)); return d;
}

// ---------------------------------------------------------------------------
// Projection GEMM, K-split 4x for warp supply:
//   partial[ks][z][m][n] = sum_{k in ks-slice} A_z[m][k] * W1[z*768 + k][n]
// Tile 32(M) x 64(N) x 192(K), 128 threads, per-thread 4x4 via packed f32x2 FMA.
// Grid (32, 12, 4) = 1536 blocks -> ~10 blocks/SM, occupancy-driven latency hiding.
// ---------------------------------------------------------------------------
__global__ __launch_bounds__(128) void proj_kernel(
    const float* __restrict__ a_in, const float* __restrict__ b_in,
    const float* __restrict__ W1)
{
    const int bx = blockIdx.x;            // 0..31 -> 16 m-tiles per z, 2 z
    const int z  = bx >> 4;
    const int m0 = (bx & 15) * 32;
    const int n0 = blockIdx.y * 64;
    const int ks = blockIdx.z;
    const int kbase = ks * 192;

    const float* __restrict__ A = (z ? b_in : a_in) + kbase;
    const float* __restrict__ W = W1 + (z * 768 + kbase) * 768;
    float* C = g_abp + ks * (2 * 512 * 768) + z * (512 * 768);

    __shared__ float As[16][36];          // transposed A tile, padded
    __shared__ float Bs[16][64];

    const int tid = threadIdx.x;
    const int tx = tid & 15;              // 16 n-groups of 4
    const int ty = tid >> 4;              // 8 m-groups of 4

    UL acc[4][2];
    #pragma unroll
    for (int i = 0; i < 4; i++) { acc[i][0] = 0ull; acc[i][1] = 0ull; }

    // A-load mapping: row = tid>>2 (0..31), kq = (tid&3)*4
    const int arow = tid >> 2;
    const int akq  = (tid & 3) * 4;
    // B-load mapping (2 float4 per thread)
    const int f0 = tid, f1 = tid + 128;
    const int kr0 = f0 >> 4, nc0 = (f0 & 15) * 4;
    const int kr1 = f1 >> 4, nc1 = (f1 & 15) * 4;

    // Prefetch first K-chunk.
    float4 pa  = *(const float4*)(A + (m0 + arow) * 768 + akq);
    float4 pb0 = *(const float4*)(W + kr0 * 768 + n0 + nc0);
    float4 pb1 = *(const float4*)(W + kr1 * 768 + n0 + nc1);

    #pragma unroll 1
    for (int kb = 0; kb < 192; kb += 16) {
        __syncthreads();
        As[akq + 0][arow] = pa.x;
        As[akq + 1][arow] = pa.y;
        As[akq + 2][arow] = pa.z;
        As[akq + 3][arow] = pa.w;
        *(float4*)&Bs[kr0][nc0] = pb0;
        *(float4*)&Bs[kr1][nc1] = pb1;
        __syncthreads();

        if (kb + 16 < 192) {
            pa  = *(const float4*)(A + (m0 + arow) * 768 + kb + 16 + akq);
            pb0 = *(const float4*)(W + (kb + 16 + kr0) * 768 + n0 + nc0);
            pb1 = *(const float4*)(W + (kb + 16 + kr1) * 768 + n0 + nc1);
        }

        #pragma unroll
        for (int k = 0; k < 16; k++) {
            float4 av = *(const float4*)&As[k][ty * 4];
            UL bv0 = *(const UL*)&Bs[k][tx * 4];
            UL bv1 = *(const UL*)&Bs[k][tx * 4 + 2];
            float aa[4] = {av.x, av.y, av.z, av.w};
            #pragma unroll
            for (int i = 0; i < 4; i++) {
                UL ap = pack_dup(aa[i]);
                acc[i][0] = fma2(ap, bv0, acc[i][0]);
                acc[i][1] = fma2(ap, bv1, acc[i][1]);
            }
        }
    }

    #pragma unroll
    for (int i = 0; i < 4; i++) {
        int m = m0 + ty * 4 + i;
        int n = n0 + tx * 4;
        *(UL*)(C + m * 768 + n)     = acc[i][0];
        *(UL*)(C + m * 768 + n + 2) = acc[i][1];
    }
}

// ---------------------------------------------------------------------------
// Fold the 4 K-split partials into g_ab, adding b1 into the ha half (z==0).
// Deterministic fixed-order sums, packed f32x2. 1536 x 256 threads.
// ---------------------------------------------------------------------------
__global__ __launch_bounds__(256) void reduce_ab_kernel(const float* __restrict__ b1)
{
    int idx = blockIdx.x * 256 + threadIdx.x;   // 0..393215, 2 floats each
    int off = idx * 2;
    UL s = *(const UL*)(g_abp + off);
    #pragma unroll
    for (int ks = 1; ks < 4; ks++)
        s = add2(s, *(const UL*)(g_abp + ks * (2 * 512 * 768) + off));
    if (off < 512 * 768)                         // z == 0: fold b1 into ha
        s = add2(s, *(const UL*)(b1 + (off % 768)));
    *(UL*)(g_ab + off) = s;
}

// ---------------------------------------------------------------------------
// Pairwise epilogue: part[hz][b][s][t][o] = sum_{h in chunk} relu(ha[s][h]+hb[t][h]) * W2[h][o]
// 64x64 (s,t) tile, 256 threads, per-thread 4x4 pairs, H split 8 ways (chunk=96).
// Grid: (4 tiles, 4 batch, 8 hsplit) = 128 blocks -> one wave.
// ---------------------------------------------------------------------------
__global__ __launch_bounds__(256) void pair_kernel(const float* __restrict__ W2)
{
    const int bx = blockIdx.x;           // 2 s-tiles x 2 t-tiles
    const int bb = blockIdx.y;           // batch
    const int bz = blockIdx.z;           // h split
    const int s0 = (bx & 1) * 64;
    const int t0 = (bx >> 1) * 64;
    const int h0 = bz * 96;

    const float* __restrict__ ha = g_ab + (bb * 128 + s0) * 768 + h0;
    const float* __restrict__ hb = g_ab + 512 * 768 + (bb * 128 + t0) * 768 + h0;

    __shared__ float  sha[32][68];       // [k][s], padded
    __shared__ float  shb[32][68];       // [k][t]
    __shared__ float2 sw2[32];

    const int tid = threadIdx.x;
    const int tx = tid & 15;             // 16 t-groups of 4
    const int ty = tid >> 4;             // 16 s-groups of 4

    float acc[4][4][2];
    #pragma unroll
    for (int i = 0; i < 4; i++)
        #pragma unroll
        for (int j = 0; j < 4; j++) { acc[i][j][0] = 0.f; acc[i][j][1] = 0.f; }

    #pragma unroll 1
    for (int kb = 0; kb < 96; kb += 32) {
        __syncthreads();
        #pragma unroll
        for (int i = 0; i < 2; i++) {
            int f = tid + i * 256;
            int si = f & 63;
            int kq = (f >> 6) * 4;
            float4 v = *(const float4*)(ha + si * 768 + kb + kq);
            sha[kq + 0][si] = v.x; sha[kq + 1][si] = v.y;
            sha[kq + 2][si] = v.z; sha[kq + 3][si] = v.w;
            float4 w = *(const float4*)(hb + si * 768 + kb + kq);
            shb[kq + 0][si] = w.x; shb[kq + 1][si] = w.y;
            shb[kq + 2][si] = w.z; shb[kq + 3][si] = w.w;
        }
        if (tid < 32) sw2[tid] = *(const float2*)(W2 + (h0 + kb + tid) * 2);
        __syncthreads();

        #pragma unroll
        for (int k = 0; k < 32; k++) {
            float4 av = *(const float4*)&sha[k][ty * 4];
            float4 bv = *(const float4*)&shb[k][tx * 4];
            float2 w  = sw2[k];
            float aa[4] = {av.x, av.y, av.z, av.w};
            float bb4[4] = {bv.x, bv.y, bv.z, bv.w};
            #pragma unroll
            for (int i = 0; i < 4; i++)
                #pragma unroll
                for (int j = 0; j < 4; j++) {
                    float x = aa[i] + bb4[j];
                    float v = fmaxf(x, 0.0f);
                    acc[i][j][0] += v * w.x;
                    acc[i][j][1] += v * w.y;
                }
        }
    }

    float* P = g_part + (bz * 4 + bb) * (128 * 128 * 2);
    #pragma unroll
    for (int i = 0; i < 4; i++)
        #pragma unroll
        for (int j = 0; j < 4; j++) {
            int s = s0 + ty * 4 + i;
            int t = t0 + tx * 4 + j;
            *(float2*)(P + (s * 128 + t) * 2) = make_float2(acc[i][j][0], acc[i][j][1]);
        }
}

// ---------------------------------------------------------------------------
// Reduce the 8 h-split partials + output bias. Deterministic (no atomics).
// ---------------------------------------------------------------------------
__global__ void reduce_kernel(const float* __restrict__ b2, float* __restrict__ out)
{
    int idx = blockIdx.x * 256 + threadIdx.x;   // pair index 0..65535
    float2 acc = *(const float2*)b2;
    #pragma unroll
    for (int zz = 0; zz < 8; zz++) {
        float2 p = *(const float2*)(g_part + zz * (4 * 128 * 128 * 2) + idx * 2);
        acc.x += p.x; acc.y += p.y;
    }
    *(float2*)(out + idx * 2) = acc;
}

extern "C" void kernel_launch(void* const* d_in, const int* in_sizes, int n_in,
                              void* d_out, int out_size)
{
    const float* a  = (const float*)d_in[0];
    const float* b  = (const float*)d_in[1];
    const float* W1 = (const float*)d_in[2];
    const float* b1 = (const float*)d_in[3];
    const float* W2 = (const float*)d_in[4];
    const float* b2 = (const float*)d_in[5];
    float* out = (float*)d_out;

    proj_kernel<<<dim3(32, 12, 4), 128>>>(a, b, W1);
    reduce_ab_kernel<<<1536, 256>>>(b1);
    pair_kernel<<<dim3(4, 4, 8), 256>>>(W2);
    reduce_kernel<<<256, 256>>>(b2, out);
}

// round 11
// speedup vs baseline: 1.1095x; 1.1095x over previous
#include <cuda_runtime.h>
#include <cuda_bf16.h>
#include <cstdint>

// ---------------------------------------------------------------------------
// Scratch (no allocs allowed).
// ---------------------------------------------------------------------------
__device__ unsigned short g_Ah[2 * 512 * 768];   // bf16 hi of [a;b], row-major [z][m][k]
__device__ unsigned short g_Al[2 * 512 * 768];   // bf16 lo
__device__ unsigned short g_Wh[2 * 768 * 768];   // bf16 hi of W1, TRANSPOSED: [z][n][k]
__device__ unsigned short g_Wl[2 * 768 * 768];   // bf16 lo
__device__ float g_ab[2 * 512 * 768];            // [z][m][H] (z=0: ha+b1, z=1: hb)
__device__ float g_part[8 * 4 * 128 * 128 * 2];  // [hsplit][b][s][t][o]

// ---------------------------------------------------------------------------
// Warp-level bf16 MMA (base sm_80+ ISA — works under the harness's compute_103
// target, unlike tcgen05 which needs the 'a' feature set).
// ---------------------------------------------------------------------------
__device__ __forceinline__ void mma16816(float* c, const uint32_t* a, const uint32_t* b) {
    asm volatile(
        "mma.sync.aligned.m16n8k16.row.col.f32.bf16.bf16.f32 "
        "{%0,%1,%2,%3}, {%4,%5,%6,%7}, {%8,%9}, {%0,%1,%2,%3};"
        : "+f"(c[0]), "+f"(c[1]), "+f"(c[2]), "+f"(c[3])
        : "r"(a[0]), "r"(a[1]), "r"(a[2]), "r"(a[3]), "r"(b[0]), "r"(b[1]));
}

// ---------------------------------------------------------------------------
// conv_a: fp32 -> bf16 hi/lo for [a;b] as one [2*512, 768] matrix.
// ---------------------------------------------------------------------------
__global__ __launch_bounds__(256) void conv_a_kernel(const float* __restrict__ a,
                                                     const float* __restrict__ b)
{
    int i = blockIdx.x * 256 + threadIdx.x;           // float4 index, < 196608
    const float* src = (i < 98304) ? (a + (size_t)i * 4) : (b + (size_t)(i - 98304) * 4);
    float4 v = *(const float4*)src;
    float x[4] = {v.x, v.y, v.z, v.w};
    ushort4 hv, lv;
    unsigned short* hp = &hv.x;
    unsigned short* lp = &lv.x;
    #pragma unroll
    for (int j = 0; j < 4; j++) {
        __nv_bfloat16 h = __float2bfloat16(x[j]);
        __nv_bfloat16 l = __float2bfloat16(x[j] - __bfloat162float(h));
        hp[j] = *(unsigned short*)&h;
        lp[j] = *(unsigned short*)&l;
    }
    *(ushort4*)(g_Ah + (size_t)i * 4) = hv;
    *(ushort4*)(g_Al + (size_t)i * 4) = lv;
}

// ---------------------------------------------------------------------------
// conv_w: fp32 W1[1536][768] -> transposed bf16 hi/lo Wt[z][n][k] (k within z).
// 32x32 tile transpose through shared.
// ---------------------------------------------------------------------------
__global__ __launch_bounds__(256) void conv_w_kernel(const float* __restrict__ W1)
{
    __shared__ float tile[32][33];
    const int n0 = blockIdx.x * 32;
    const int k0 = blockIdx.y * 32;                   // global k over 1536
    const int tx = threadIdx.x, ty = threadIdx.y;     // (32, 8)
    #pragma unroll
    for (int i = 0; i < 4; i++)
        tile[ty + 8 * i][tx] = W1[(size_t)(k0 + ty + 8 * i) * 768 + n0 + tx];
    __syncthreads();
    const int z = (k0 >= 768) ? 1 : 0;
    const int kk = k0 - z * 768 + tx;                 // k within z
    #pragma unroll
    for (int i = 0; i < 4; i++) {
        int n = n0 + ty + 8 * i;
        float x = tile[tx][ty + 8 * i];               // = W1[k0+tx][n]
        __nv_bfloat16 h = __float2bfloat16(x);
        __nv_bfloat16 l = __float2bfloat16(x - __bfloat162float(h));
        size_t o = (size_t)z * 768 * 768 + (size_t)n * 768 + kk;
        g_Wh[o] = *(unsigned short*)&h;
        g_Wl[o] = *(unsigned short*)&l;
    }
}

// ---------------------------------------------------------------------------
// Tensor-core projection via mma.sync (HMMA):
//   g_ab[z][m][n] = sum_k A_z[m][k]*W1_z[k][n] (+b1 if z==0)
// bf16-split 3-term: Ah*Wh + Al*Wh + Ah*Wl (Al*Wl ~2^-16, dropped).
// CTA: 64M x 64N, 128 threads = 4 warps in 2x2, warp tile 32x32 (2x4 frags).
// K-chunks of 32; Ah/Al/Wh/Wl tiles all in SMEM (40-elem row pad, LDS
// conflict-free for the m16n8k16 fragment access pattern).
// Grid (8, 12, 2) = 192 CTAs.
// ---------------------------------------------------------------------------
__global__ __launch_bounds__(128) void mma_proj_kernel(const float* __restrict__ b1)
{
    __shared__ __align__(16) unsigned short AsH[64][40];
    __shared__ __align__(16) unsigned short AsL[64][40];
    __shared__ __align__(16) unsigned short WsH[64][40];
    __shared__ __align__(16) unsigned short WsL[64][40];

    const int tid = threadIdx.x;
    const int wid = tid >> 5;
    const int lid = tid & 31;
    const int g = lid >> 2;              // fragment row group 0..7
    const int t = lid & 3;               // thread-in-group 0..3
    const int m0 = blockIdx.x * 64;
    const int n0 = blockIdx.y * 64;
    const int z  = blockIdx.z;
    const int wm = (wid & 1) * 32;
    const int wn = (wid >> 1) * 32;

    const unsigned short* __restrict__ Ah = g_Ah + (size_t)z * 512 * 768;
    const unsigned short* __restrict__ Al = g_Al + (size_t)z * 512 * 768;
    const unsigned short* __restrict__ Wh = g_Wh + (size_t)z * 768 * 768;
    const unsigned short* __restrict__ Wl = g_Wl + (size_t)z * 768 * 768;

    float acc[2][4][4];
    #pragma unroll
    for (int mf = 0; mf < 2; mf++)
        #pragma unroll
        for (int nf = 0; nf < 4; nf++)
            #pragma unroll
            for (int q = 0; q < 4; q++) acc[mf][nf][q] = 0.f;

    #pragma unroll 1
    for (int kb = 0; kb < 768; kb += 32) {
        __syncthreads();
        #pragma unroll
        for (int i = 0; i < 2; i++) {
            int v = tid + i * 128;
            int row = v >> 2;            // 0..63
            int kq  = (v & 3) * 8;       // 0,8,16,24
            size_t ga = (size_t)(m0 + row) * 768 + kb + kq;
            size_t gw = (size_t)(n0 + row) * 768 + kb + kq;
            *(uint4*)&AsH[row][kq] = *(const uint4*)(Ah + ga);
            *(uint4*)&AsL[row][kq] = *(const uint4*)(Al + ga);
            *(uint4*)&WsH[row][kq] = *(const uint4*)(Wh + gw);
            *(uint4*)&WsL[row][kq] = *(const uint4*)(Wl + gw);
        }
        __syncthreads();

        #pragma unroll
        for (int ks = 0; ks < 2; ks++) {
            const int k0 = ks * 16 + t * 2;
            uint32_t ah[2][4], al[2][4], bh[4][2], bl[4][2];
            #pragma unroll
            for (int mf = 0; mf < 2; mf++) {
                int mb = wm + mf * 16 + g;
                ah[mf][0] = *(const uint32_t*)&AsH[mb][k0];
                ah[mf][1] = *(const uint32_t*)&AsH[mb + 8][k0];
                ah[mf][2] = *(const uint32_t*)&AsH[mb][k0 + 8];
                ah[mf][3] = *(const uint32_t*)&AsH[mb + 8][k0 + 8];
                al[mf][0] = *(const uint32_t*)&AsL[mb][k0];
                al[mf][1] = *(const uint32_t*)&AsL[mb + 8][k0];
                al[mf][2] = *(const uint32_t*)&AsL[mb][k0 + 8];
                al[mf][3] = *(const uint32_t*)&AsL[mb + 8][k0 + 8];
            }
            #pragma unroll
            for (int nf = 0; nf < 4; nf++) {
                int nb = wn + nf * 8 + g;
                bh[nf][0] = *(const uint32_t*)&WsH[nb][k0];
                bh[nf][1] = *(const uint32_t*)&WsH[nb][k0 + 8];
                bl[nf][0] = *(const uint32_t*)&WsL[nb][k0];
                bl[nf][1] = *(const uint32_t*)&WsL[nb][k0 + 8];
            }
            #pragma unroll
            for (int mf = 0; mf < 2; mf++)
                #pragma unroll
                for (int nf = 0; nf < 4; nf++) {
                    mma16816(acc[mf][nf], ah[mf], bh[nf]);
                    mma16816(acc[mf][nf], al[mf], bh[nf]);
                    mma16816(acc[mf][nf], ah[mf], bl[nf]);
                }
        }
    }

    // Epilogue: fragment layout d0/d1 = row g cols 2t,2t+1; d2/d3 = row g+8.
    float* C = g_ab + (size_t)z * 512 * 768;
    #pragma unroll
    for (int mf = 0; mf < 2; mf++) {
        int mr = m0 + wm + mf * 16 + g;
        #pragma unroll
        for (int nf = 0; nf < 4; nf++) {
            int n = n0 + wn + nf * 8 + t * 2;
            float2 add = make_float2(0.f, 0.f);
            if (z == 0) add = *(const float2*)(b1 + n);
            *(float2*)(C + (size_t)mr * 768 + n) =
                make_float2(acc[mf][nf][0] + add.x, acc[mf][nf][1] + add.y);
            *(float2*)(C + (size_t)(mr + 8) * 768 + n) =
                make_float2(acc[mf][nf][2] + add.x, acc[mf][nf][3] + add.y);
        }
    }
}

// ---------------------------------------------------------------------------
// Pairwise epilogue: part[hz][b][s][t][o] = sum_{h in chunk} relu(ha[s][h]+hb[t][h]) * W2[h][o]
// 64x64 (s,t) tile, 256 threads, per-thread 4x4 pairs, H split 8 ways (chunk=96).
// Grid: (4 tiles, 4 batch, 8 hsplit) = 128 blocks -> one wave.
// ---------------------------------------------------------------------------
__global__ __launch_bounds__(256) void pair_kernel(const float* __restrict__ W2)
{
    const int bx = blockIdx.x;           // 2 s-tiles x 2 t-tiles
    const int bb = blockIdx.y;           // batch
    const int bz = blockIdx.z;           // h split
    const int s0 = (bx & 1) * 64;
    const int t0 = (bx >> 1) * 64;
    const int h0 = bz * 96;

    const float* __restrict__ ha = g_ab + (bb * 128 + s0) * 768 + h0;
    const float* __restrict__ hb = g_ab + 512 * 768 + (bb * 128 + t0) * 768 + h0;

    __shared__ float  sha[32][68];       // [k][s], padded
    __shared__ float  shb[32][68];       // [k][t]
    __shared__ float2 sw2[32];

    const int tid = threadIdx.x;
    const int tx = tid & 15;             // 16 t-groups of 4
    const int ty = tid >> 4;             // 16 s-groups of 4

    float acc[4][4][2];
    #pragma unroll
    for (int i = 0; i < 4; i++)
        #pragma unroll
        for (int j = 0; j < 4; j++) { acc[i][j][0] = 0.f; acc[i][j][1] = 0.f; }

    #pragma unroll 1
    for (int kb = 0; kb < 96; kb += 32) {
        __syncthreads();
        #pragma unroll
        for (int i = 0; i < 2; i++) {
            int f = tid + i * 256;
            int si = f & 63;
            int kq = (f >> 6) * 4;
            float4 v = *(const float4*)(ha + si * 768 + kb + kq);
            sha[kq + 0][si] = v.x; sha[kq + 1][si] = v.y;
            sha[kq + 2][si] = v.z; sha[kq + 3][si] = v.w;
            float4 w = *(const float4*)(hb + si * 768 + kb + kq);
            shb[kq + 0][si] = w.x; shb[kq + 1][si] = w.y;
            shb[kq + 2][si] = w.z; shb[kq + 3][si] = w.w;
        }
        if (tid < 32) sw2[tid] = *(const float2*)(W2 + (h0 + kb + tid) * 2);
        __syncthreads();

        #pragma unroll
        for (int k = 0; k < 32; k++) {
            float4 av = *(const float4*)&sha[k][ty * 4];
            float4 bv = *(const float4*)&shb[k][tx * 4];
            float2 w  = sw2[k];
            float aa[4] = {av.x, av.y, av.z, av.w};
            float bb4[4] = {bv.x, bv.y, bv.z, bv.w};
            #pragma unroll
            for (int i = 0; i < 4; i++)
                #pragma unroll
                for (int j = 0; j < 4; j++) {
                    float x = aa[i] + bb4[j];
                    float v = fmaxf(x, 0.0f);
                    acc[i][j][0] += v * w.x;
                    acc[i][j][1] += v * w.y;
                }
        }
    }

    float* P = g_part + (bz * 4 + bb) * (128 * 128 * 2);
    #pragma unroll
    for (int i = 0; i < 4; i++)
        #pragma unroll
        for (int j = 0; j < 4; j++) {
            int s = s0 + ty * 4 + i;
            int t = t0 + tx * 4 + j;
            *(float2*)(P + (s * 128 + t) * 2) = make_float2(acc[i][j][0], acc[i][j][1]);
        }
}

// ---------------------------------------------------------------------------
// Reduce the 8 h-split partials + output bias. float4 per thread (2 pairs).
// ---------------------------------------------------------------------------
__global__ __launch_bounds__(256) void reduce_kernel(const float* __restrict__ b2,
                                                     float* __restrict__ out)
{
    int idx = blockIdx.x * 256 + threadIdx.x;   // 0..32767, 2 pairs each
    float2 bb = *(const float2*)b2;
    float4 acc = make_float4(bb.x, bb.y, bb.x, bb.y);
    #pragma unroll
    for (int zz = 0; zz < 8; zz++) {
        float4 p = *(const float4*)(g_part + (size_t)zz * (4 * 128 * 128 * 2) + (size_t)idx * 4);
        acc.x += p.x; acc.y += p.y; acc.z += p.z; acc.w += p.w;
    }
    *(float4*)(out + (size_t)idx * 4) = acc;
}

extern "C" void kernel_launch(void* const* d_in, const int* in_sizes, int n_in,
                              void* d_out, int out_size)
{
    const float* a  = (const float*)d_in[0];
    const float* b  = (const float*)d_in[1];
    const float* W1 = (const float*)d_in[2];
    const float* b1 = (const float*)d_in[3];
    const float* W2 = (const float*)d_in[4];
    const float* b2 = (const float*)d_in[5];
    float* out = (float*)d_out;

    conv_a_kernel<<<768, 256>>>(a, b);
    conv_w_kernel<<<dim3(24, 48), dim3(32, 8)>>>(W1);
    mma_proj_kernel<<<dim3(8, 12, 2), 128>>>(b1);
    pair_kernel<<<dim3(4, 4, 8), 256>>>(W2);
    reduce_kernel<<<128, 256>>>(b2, out);
}